// round 13
// baseline (speedup 1.0000x reference)
#include <cuda_runtime.h>
#include <math.h>

#define TS_   256
#define CTS_  512
#define B_    64
#define H_    512
#define K_    10
#define H3_   1536
#define TB_   16384
#define LOG2E 1.44269504088896340736f

static const int OFF_ATTK = TB_ * H_;
static const int OFF_ATTW = TB_ * H_ + TB_ * K_;

typedef unsigned long long u64;

// ---------------- static device scratch ----------------
__device__ float    g_a   [TB_ * K_];
__device__ float    g_b2  [TB_ * K_];
__device__ float    g_kinc[TB_ * K_];
__device__ float    g_phi [TB_ * CTS_];
__device__ float    g_h   [2 * B_ * H_];
__device__ unsigned g_cnt [512];

__device__ __forceinline__ float ex2f(float x) {
    float r; asm("ex2.approx.ftz.f32 %0, %1;" : "=f"(r) : "f"(x)); return r;
}
__device__ __forceinline__ float sigmf(float x) { return 1.0f / (1.0f + __expf(-x)); }

__device__ __forceinline__ u64 pack2(float lo, float hi) {
    u64 r; asm("mov.b64 %0, {%1, %2};" : "=l"(r) : "f"(lo), "f"(hi)); return r;
}
__device__ __forceinline__ void unpack2(u64 v, float& lo, float& hi) {
    asm("mov.b64 {%0, %1}, %2;" : "=f"(lo), "=f"(hi) : "l"(v));
}
__device__ __forceinline__ u64 ffma2(u64 a, u64 b, u64 c) {
    u64 d; asm("fma.rn.f32x2 %0, %1, %2, %3;" : "=l"(d) : "l"(a), "l"(b), "l"(c)); return d;
}

// ---------------- K1: a_t, b_t, kinc_t ----------------
__global__ __launch_bounds__(256) void k_abk(
    const float* __restrict__ inp,
    const float* __restrict__ Wa, const float* __restrict__ ba,
    const float* __restrict__ Wb, const float* __restrict__ bb,
    const float* __restrict__ Wk, const float* __restrict__ bk)
{
    __shared__ float xs[8 * 516];
    int tid = threadIdx.x;
    int r0 = blockIdx.x * 8;
    #pragma unroll
    for (int c = 0; c < 4; c++) {
        int fi = c * 256 + tid;
        int r = fi >> 7, hq = fi & 127;
        float4 v = *(const float4*)&inp[(r0 + r) * 512 + hq * 4];
        *(float4*)&xs[r * 516 + hq * 4] = v;
    }
    __syncthreads();

    int r = tid >> 5, o = tid & 31;
    if (o >= 30) return;
    const float* wrow; float bias;
    if (o < 10)      { wrow = Wa + o * 512;        bias = ba[o]; }
    else if (o < 20) { wrow = Wb + (o - 10) * 512; bias = bb[o - 10]; }
    else             { wrow = Wk + (o - 20) * 512; bias = bk[o - 20]; }

    const float4* xp = (const float4*)&xs[r * 516];
    const float4* wp = (const float4*)wrow;
    float a0 = 0.f, a1 = 0.f, a2 = 0.f, a3 = 0.f;
    #pragma unroll 8
    for (int q = 0; q < 128; q++) {
        float4 x = xp[q];
        float4 w = __ldg(&wp[q]);
        a0 += x.x * w.x; a1 += x.y * w.y; a2 += x.z * w.z; a3 += x.w * w.w;
    }
    float v = expf((a0 + a1) + (a2 + a3) + bias);
    int row = r0 + r;
    if (o < 10)      g_a   [row * 10 + o]        = v;
    else if (o < 20) g_b2  [row * 10 + (o - 10)] = v * LOG2E;
    else             g_kinc[row * 10 + (o - 20)] = v;
}

// ---------------- K2: cumulative k_t (zeroes GRU counters each replay) ----------------
__global__ void k_cumsum(const float* __restrict__ att_init, float* __restrict__ out) {
    int j = blockIdx.x * 128 + threadIdx.x;
    if (j < 512) g_cnt[j] = 0;
    if (j >= 640) return;
    float acc = att_init[j];
    #pragma unroll 8
    for (int t = 0; t < TS_; t++) {
        acc += g_kinc[t * 640 + j];
        g_kinc[t * 640 + j] = acc;
        out[OFF_ATTK + t * 640 + j] = acc;
    }
}

// ---------------- K3: phi ----------------
__global__ __launch_bounds__(512) void k_phi() {
    __shared__ float sa[10], sb[10], sk[10];
    int row = blockIdx.x;
    int tid = threadIdx.x;
    if (tid < 10)       sa[tid]      = g_a   [row * 10 + tid];
    else if (tid < 20)  sb[tid - 10] = g_b2  [row * 10 + tid - 10];
    else if (tid < 30)  sk[tid - 20] = g_kinc[row * 10 + tid - 20];
    __syncthreads();
    float s = (float)tid;
    float acc = 0.f;
    #pragma unroll
    for (int k = 0; k < 10; k++) {
        float d = sk[k] - s;
        float e = sb[k] * d * d;
        if (e < 30.f) acc += sa[k] * ex2f(-e);
    }
    g_phi[row * 512 + tid] = acc;
}

// ---------------- K4: w = phi @ c_inp (R3 proven) ----------------
#define AST 264
#define BST 132

__global__ __launch_bounds__(256, 2) void k_gemm_w(
    const float* __restrict__ c_inp, float* __restrict__ outw)
{
    __shared__ float As2[16 * AST];
    __shared__ float Bs [16 * BST];
    int tid = threadIdx.x;
    int b  = blockIdx.z;
    int m0 = blockIdx.y * 128, n0 = blockIdx.x * 128;

    int lrow = tid >> 2, lq = tid & 3;
    const float* Ap0 = g_phi + b * 512 + (m0 + lrow) * 32768 + lq * 4;
    const float* Ap1 = Ap0 + 64 * 32768;
    int lk = tid >> 5, nq = tid & 31;
    const float* Bp0 = c_inp + b * 512 + lk * 32768 + n0 + nq * 4;
    const float* Bp1 = Bp0 + 8 * 32768;

    float4 aR0 = *(const float4*)(Ap0);
    float4 aR1 = *(const float4*)(Ap1);
    float4 bR0 = *(const float4*)(Bp0);
    float4 bR1 = *(const float4*)(Bp1);

    int tx = tid & 15, ty = tid >> 4;
    u64 acc[8][4];
    #pragma unroll
    for (int i = 0; i < 8; i++)
        #pragma unroll
        for (int j = 0; j < 4; j++) acc[i][j] = 0ull;

    for (int kt = 0; kt < 32; kt++) {
        __syncthreads();
        {
            int m = 2 * lrow;
            *(u64*)&As2[(lq * 4 + 0) * AST + m]       = pack2(aR0.x, aR0.x);
            *(u64*)&As2[(lq * 4 + 1) * AST + m]       = pack2(aR0.y, aR0.y);
            *(u64*)&As2[(lq * 4 + 2) * AST + m]       = pack2(aR0.z, aR0.z);
            *(u64*)&As2[(lq * 4 + 3) * AST + m]       = pack2(aR0.w, aR0.w);
            *(u64*)&As2[(lq * 4 + 0) * AST + m + 128] = pack2(aR1.x, aR1.x);
            *(u64*)&As2[(lq * 4 + 1) * AST + m + 128] = pack2(aR1.y, aR1.y);
            *(u64*)&As2[(lq * 4 + 2) * AST + m + 128] = pack2(aR1.z, aR1.z);
            *(u64*)&As2[(lq * 4 + 3) * AST + m + 128] = pack2(aR1.w, aR1.w);
            *(float4*)&Bs[lk * BST + nq * 4]       = bR0;
            *(float4*)&Bs[(lk + 8) * BST + nq * 4] = bR1;
        }
        __syncthreads();
        if (kt < 31) {
            aR0 = *(const float4*)(Ap0 + (kt + 1) * 16);
            aR1 = *(const float4*)(Ap1 + (kt + 1) * 16);
            bR0 = *(const float4*)(Bp0 + (kt + 1) * 16 * 32768);
            bR1 = *(const float4*)(Bp1 + (kt + 1) * 16 * 32768);
        }
        #pragma unroll
        for (int kk = 0; kk < 16; kk++) {
            ulonglong2 a01 = *(const ulonglong2*)&As2[kk * AST + 8 * ty];
            ulonglong2 a23 = *(const ulonglong2*)&As2[kk * AST + 8 * ty + 4];
            ulonglong2 a45 = *(const ulonglong2*)&As2[kk * AST + 8 * ty + 128];
            ulonglong2 a67 = *(const ulonglong2*)&As2[kk * AST + 8 * ty + 132];
            ulonglong2 b01 = *(const ulonglong2*)&Bs[kk * BST + tx * 4];
            ulonglong2 b23 = *(const ulonglong2*)&Bs[kk * BST + tx * 4 + 64];
            u64 av[8] = {a01.x, a01.y, a23.x, a23.y, a45.x, a45.y, a67.x, a67.y};
            u64 bv[4] = {b01.x, b01.y, b23.x, b23.y};
            #pragma unroll
            for (int i = 0; i < 8; i++)
                #pragma unroll
                for (int j = 0; j < 4; j++)
                    acc[i][j] = ffma2(av[i], bv[j], acc[i][j]);
        }
    }
    float* C = outw + b * 512;
    #pragma unroll
    for (int i = 0; i < 8; i++) {
        int m = m0 + ((i < 4) ? (ty * 4 + i) : (ty * 4 + 64 + i - 4));
        float c0, c1, c2, c3;
        unpack2(acc[i][0], c0, c1); unpack2(acc[i][1], c2, c3);
        *(float4*)&C[(size_t)m * 32768 + n0 + tx * 4] = make_float4(c0, c1, c2, c3);
        unpack2(acc[i][2], c0, c1); unpack2(acc[i][3], c2, c3);
        *(float4*)&C[(size_t)m * 32768 + n0 + tx * 4 + 64] = make_float4(c0, c1, c2, c3);
    }
}

// ---------------- K6: persistent GRU with inlined gi GEMM ----------------
// grid (32 ug, 4 bg) x 384 threads, 1 block/SM.
//   tid 0..127  : GRU compute (R8 proven: u=tid>>3, bp=tid&7, batches bp,bp+8).
//                 Reads gi from SMEM gibuf[t&1].
//   tid 128..255: gi warps — during step t: stage w[t+1] rows, compute
//                 gi[t+1] slice (48 cols x 16 batches) into gibuf[(t+1)&1].
//   tid 256..383: staging warps — poll bg counter, restage h into ping-pong.
// Named barriers: 1 = all 384 (step start: h[t] staged + gi[t] ready),
//                 2 = compute 128, 3 = staging 128, 5 = gi 128.
#define HROW   516
#define HBUF_F (16 * HROW)                 // 8256 floats per h buffer
#define WSM_OFF (2 * HBUF_F)               // W_hh rows, stride 512
#define WST_OFF (WSM_OFF + 48 * 512)       // staged w rows, stride 516
#define GIB_OFF (WST_OFF + 16 * 516)       // gi buffers [2][16][52]
#define GRU_SMEM ((GIB_OFF + 2 * 16 * 52) * 4)

__global__ __launch_bounds__(384, 1) void k_gru(
    const float* __restrict__ gru_init,
    const float* __restrict__ W_hh, const float* __restrict__ b_hh,
    const float* __restrict__ W_ih, const float* __restrict__ b_ih,
    const float* __restrict__ wsrc,
    float* __restrict__ out)
{
    extern __shared__ float sm[];
    float* hbuf = sm;                      // [2][16][HROW]
    float* Wsm  = sm + WSM_OFF;            // [48][512], row = gate*16 + u
    float* wst  = sm + WST_OFF;            // [16][516]
    float* gib  = sm + GIB_OFF;            // [2][16][52]
    int tid = threadIdx.x;
    int ug = blockIdx.x, bg = blockIdx.y;

    for (int f = tid; f < 48 * 128; f += 384) {
        int rr = f >> 7, c = f & 127;
        int gate = rr >> 4, uu = rr & 15;
        float4 v = *(const float4*)&W_hh[((size_t)(gate * 512 + ug * 16 + uu)) * 512 + c * 4];
        *(float4*)&Wsm[rr * 512 + c * 4] = v;
    }
    __syncthreads();

    if (tid < 128) {
        // ================= GRU compute warps =================
        int u  = tid >> 3;
        int bp = tid & 7;
        int gu  = ug * 16 + u;
        int gb0 = bg * 16 + bp;
        int gb1 = gb0 + 8;
        float bhr = b_hh[gu], bhz = b_hh[512 + gu], bhn = b_hh[1024 + gu];
        const float* wr = &Wsm[(0  + u) * 512];
        const float* wz = &Wsm[(16 + u) * 512];
        const float* wn = &Wsm[(32 + u) * 512];

        for (int t = 0; t < TS_; t++) {
            asm volatile("bar.sync 1, 384;" ::: "memory");   // h[t] staged + gi[t] ready

            // gi from SMEM (computed last step by gi warps)
            const float* gbp = &gib[(t & 1) * 832];
            float giR0 = gbp[bp * 52 + u];
            float giZ0 = gbp[bp * 52 + 16 + u];
            float giN0 = gbp[bp * 52 + 32 + u];
            float giR1 = gbp[(bp + 8) * 52 + u];
            float giZ1 = gbp[(bp + 8) * 52 + 16 + u];
            float giN1 = gbp[(bp + 8) * 52 + 32 + u];

            const float* hb = &hbuf[(t & 1) * HBUF_F];
            const float* h0 = &hb[bp * HROW];
            const float* h1 = h0 + 8 * HROW;
            u64 aR0 = 0, aZ0 = 0, aN0 = 0, aR1 = 0, aZ1 = 0, aN1 = 0;
            #pragma unroll 8
            for (int hh = 0; hh < 512; hh += 4) {
                ulonglong2 hv0 = *(const ulonglong2*)&h0[hh];
                ulonglong2 hv1 = *(const ulonglong2*)&h1[hh];
                ulonglong2 r2 = *(const ulonglong2*)&wr[hh];
                ulonglong2 z2 = *(const ulonglong2*)&wz[hh];
                ulonglong2 n2 = *(const ulonglong2*)&wn[hh];
                aR0 = ffma2(hv0.x, r2.x, aR0); aR0 = ffma2(hv0.y, r2.y, aR0);
                aZ0 = ffma2(hv0.x, z2.x, aZ0); aZ0 = ffma2(hv0.y, z2.y, aZ0);
                aN0 = ffma2(hv0.x, n2.x, aN0); aN0 = ffma2(hv0.y, n2.y, aN0);
                aR1 = ffma2(hv1.x, r2.x, aR1); aR1 = ffma2(hv1.y, r2.y, aR1);
                aZ1 = ffma2(hv1.x, z2.x, aZ1); aZ1 = ffma2(hv1.y, z2.y, aZ1);
                aN1 = ffma2(hv1.x, n2.x, aN1); aN1 = ffma2(hv1.y, n2.y, aN1);
            }
            float lo, hi;
            unpack2(aR0, lo, hi); float sR0 = lo + hi;
            unpack2(aZ0, lo, hi); float sZ0 = lo + hi;
            unpack2(aN0, lo, hi); float sN0 = lo + hi;
            unpack2(aR1, lo, hi); float sR1 = lo + hi;
            unpack2(aZ1, lo, hi); float sZ1 = lo + hi;
            unpack2(aN1, lo, hi); float sN1 = lo + hi;

            float hp0 = hb[bp * HROW + gu];
            float hp1 = hb[(bp + 8) * HROW + gu];
            float r0 = sigmf(giR0 + sR0 + bhr);
            float z0 = sigmf(giZ0 + sZ0 + bhz);
            float n0v = tanhf(giN0 + r0 * (sN0 + bhn));
            float hn0 = (1.f - z0) * n0v + z0 * hp0;
            float r1 = sigmf(giR1 + sR1 + bhr);
            float z1 = sigmf(giZ1 + sZ1 + bhz);
            float n1v = tanhf(giN1 + r1 * (sN1 + bhn));
            float hn1 = (1.f - z1) * n1v + z1 * hp1;

            if (t < TS_ - 1) {
                g_h[((t + 1) & 1) * 32768 + gb0 * 512 + gu] = hn0;
                g_h[((t + 1) & 1) * 32768 + gb1 * 512 + gu] = hn1;
                asm volatile("bar.sync 2, 128;" ::: "memory");
                if (tid == 0) {
                    __threadfence();
                    atomicAdd(&g_cnt[bg * 32], 1u);
                }
            }
            out[(size_t)t * 32768 + gb0 * 512 + gu] = hn0;
            out[(size_t)t * 32768 + gb1 * 512 + gu] = hn1;
        }
    } else if (tid < 256) {
        // ================= gi warps =================
        int gtid = tid - 128;
        int u  = gtid & 15;
        int bq = gtid >> 4;                 // 0..7; batches bq, bq+8 (local)
        int gu = ug * 16 + u;
        const float* wihR = W_ih + (size_t)gu * 512;
        const float* wihZ = W_ih + (size_t)(512 + gu) * 512;
        const float* wihN = W_ih + (size_t)(1024 + gu) * 512;
        float biR = b_ih[gu], biZ = b_ih[512 + gu], biN = b_ih[1024 + gu];

        // compute gi for timestep tt into gib[tt&1]
        auto gi_step = [&](int tt) {
            // stage w[tt] rows (16 x 512 = 2048 float4 / 128 threads)
            const float* src = wsrc + ((size_t)tt * 64 + bg * 16) * 512;
            #pragma unroll
            for (int c = 0; c < 16; c++) {
                int i = c * 128 + gtid;
                float4 v = __ldcg((const float4*)&src[(i >> 7) * 512 + (i & 127) * 4]);
                *(float4*)&wst[(i >> 7) * 516 + (i & 127) * 4] = v;
            }
            asm volatile("bar.sync 5, 128;" ::: "memory");
            const float* w0 = &wst[bq * 516];
            const float* w1 = w0 + 8 * 516;
            u64 aR0 = 0, aZ0 = 0, aN0 = 0, aR1 = 0, aZ1 = 0, aN1 = 0;
            #pragma unroll 8
            for (int k = 0; k < 512; k += 4) {
                ulonglong2 wv0 = *(const ulonglong2*)&w0[k];
                ulonglong2 wv1 = *(const ulonglong2*)&w1[k];
                ulonglong2 rr = *(const ulonglong2*)&wihR[k];
                ulonglong2 zz = *(const ulonglong2*)&wihZ[k];
                ulonglong2 nn = *(const ulonglong2*)&wihN[k];
                aR0 = ffma2(wv0.x, rr.x, aR0); aR0 = ffma2(wv0.y, rr.y, aR0);
                aZ0 = ffma2(wv0.x, zz.x, aZ0); aZ0 = ffma2(wv0.y, zz.y, aZ0);
                aN0 = ffma2(wv0.x, nn.x, aN0); aN0 = ffma2(wv0.y, nn.y, aN0);
                aR1 = ffma2(wv1.x, rr.x, aR1); aR1 = ffma2(wv1.y, rr.y, aR1);
                aZ1 = ffma2(wv1.x, zz.x, aZ1); aZ1 = ffma2(wv1.y, zz.y, aZ1);
                aN1 = ffma2(wv1.x, nn.x, aN1); aN1 = ffma2(wv1.y, nn.y, aN1);
            }
            float lo, hi;
            float* gbp = &gib[(tt & 1) * 832];
            unpack2(aR0, lo, hi); gbp[bq * 52 + u]            = lo + hi + biR;
            unpack2(aZ0, lo, hi); gbp[bq * 52 + 16 + u]       = lo + hi + biZ;
            unpack2(aN0, lo, hi); gbp[bq * 52 + 32 + u]       = lo + hi + biN;
            unpack2(aR1, lo, hi); gbp[(bq + 8) * 52 + u]      = lo + hi + biR;
            unpack2(aZ1, lo, hi); gbp[(bq + 8) * 52 + 16 + u] = lo + hi + biZ;
            unpack2(aN1, lo, hi); gbp[(bq + 8) * 52 + 32 + u] = lo + hi + biN;
        };

        gi_step(0);   // prologue: gi[0] ready before first bar1
        for (int t = 0; t < TS_; t++) {
            asm volatile("bar.sync 1, 384;" ::: "memory");
            if (t + 1 < TS_) gi_step(t + 1);
        }
    } else {
        // ================= staging warps =================
        int stid = tid - 256;
        volatile unsigned* cnt = &g_cnt[bg * 32];
        for (int t = 0; t < TS_; t++) {
            const float4* src;
            if (t == 0) {
                src = (const float4*)(gru_init + bg * 8192);
            } else {
                if (stid == 0) {
                    unsigned target = 32u * (unsigned)t;
                    while (*cnt < target) { }
                    __threadfence();
                }
                asm volatile("bar.sync 3, 128;" ::: "memory");
                src = (const float4*)(g_h + (t & 1) * 32768 + bg * 8192);
            }
            float* dst = &hbuf[(t & 1) * HBUF_F];
            #pragma unroll
            for (int c = 0; c < 16; c++) {
                int i = c * 128 + stid;
                float4 v = __ldcg(&src[i]);
                *(float4*)&dst[(i >> 7) * HROW + (i & 127) * 4] = v;
            }
            asm volatile("bar.sync 1, 384;" ::: "memory");
        }
    }
}

// ---------------- host ----------------
extern "C" void kernel_launch(void* const* d_in, const int* in_sizes, int n_in,
                              void* d_out, int out_size)
{
    const float* c_inp    = (const float*)d_in[0];
    const float* inp      = (const float*)d_in[1];
    const float* gru_init = (const float*)d_in[2];
    const float* att_init = (const float*)d_in[3];
    const float* Wa = (const float*)d_in[4];  const float* ba = (const float*)d_in[5];
    const float* Wb = (const float*)d_in[6];  const float* bb = (const float*)d_in[7];
    const float* Wk = (const float*)d_in[8];  const float* bk = (const float*)d_in[9];
    const float* W_ih = (const float*)d_in[10]; const float* b_ih = (const float*)d_in[11];
    const float* W_hh = (const float*)d_in[12]; const float* b_hh = (const float*)d_in[13];
    float* out = (float*)d_out;

    cudaFuncSetAttribute(k_gru, cudaFuncAttributeMaxDynamicSharedMemorySize, GRU_SMEM);

    k_abk    <<<2048, 256>>>(inp, Wa, ba, Wb, bb, Wk, bk);
    k_cumsum <<<5, 128>>>(att_init, out);
    k_phi    <<<16384, 512>>>();
    k_gemm_w <<<dim3(4, 2, 64), 256>>>(c_inp, out + OFF_ATTW);
    k_gru    <<<dim3(32, 4), 384, GRU_SMEM>>>(gru_init, W_hh, b_hh, W_ih, b_ih,
                                              out + OFF_ATTW, out);
}

// round 14
// speedup vs baseline: 3.1732x; 3.1732x over previous
#include <cuda_runtime.h>
#include <math.h>

#define TS_   256
#define CTS_  512
#define B_    64
#define H_    512
#define K_    10
#define H3_   1536
#define TB_   16384
#define LOG2E 1.44269504088896340736f

static const int OFF_ATTK = TB_ * H_;
static const int OFF_ATTW = TB_ * H_ + TB_ * K_;

typedef unsigned long long u64;

// ---------------- static device scratch ----------------
__device__ float    g_a   [TB_ * K_];
__device__ float    g_b2  [TB_ * K_];
__device__ float    g_kinc[TB_ * K_];
__device__ float    g_phi [TB_ * CTS_];
__device__ float    g_gi  [TB_ * H3_];
__device__ float    g_h   [2 * B_ * H_];
__device__ unsigned g_cnt [512];
__device__ unsigned g_done = 0;
__device__ unsigned g_wcnt = 0;

__device__ __forceinline__ float ex2f(float x) {
    float r; asm("ex2.approx.ftz.f32 %0, %1;" : "=f"(r) : "f"(x)); return r;
}
__device__ __forceinline__ float sigmf(float x) { return 1.0f / (1.0f + __expf(-x)); }

__device__ __forceinline__ u64 pack2(float lo, float hi) {
    u64 r; asm("mov.b64 %0, {%1, %2};" : "=l"(r) : "f"(lo), "f"(hi)); return r;
}
__device__ __forceinline__ void unpack2(u64 v, float& lo, float& hi) {
    asm("mov.b64 {%0, %1}, %2;" : "=f"(lo), "=f"(hi) : "l"(v));
}
__device__ __forceinline__ u64 ffma2(u64 a, u64 b, u64 c) {
    u64 d; asm("fma.rn.f32x2 %0, %1, %2, %3;" : "=l"(d) : "l"(a), "l"(b), "l"(c)); return d;
}

// ---------------- K1: a_t, b_t, kinc_t  (+ last-block cumsum & counter init) ----------------
__global__ __launch_bounds__(256) void k_abk_cum(
    const float* __restrict__ inp,
    const float* __restrict__ Wa, const float* __restrict__ ba,
    const float* __restrict__ Wb, const float* __restrict__ bb,
    const float* __restrict__ Wk, const float* __restrict__ bk,
    const float* __restrict__ att_init, float* __restrict__ out)
{
    __shared__ float xs[8 * 516];
    __shared__ unsigned s_last;
    int tid = threadIdx.x;
    int r0 = blockIdx.x * 8;
    #pragma unroll
    for (int c = 0; c < 4; c++) {
        int fi = c * 256 + tid;
        int r = fi >> 7, hq = fi & 127;
        float4 v = *(const float4*)&inp[(r0 + r) * 512 + hq * 4];
        *(float4*)&xs[r * 516 + hq * 4] = v;
    }
    __syncthreads();

    int r = tid >> 5, o = tid & 31;
    if (o < 30) {
        const float* wrow; float bias;
        if (o < 10)      { wrow = Wa + o * 512;        bias = ba[o]; }
        else if (o < 20) { wrow = Wb + (o - 10) * 512; bias = bb[o - 10]; }
        else             { wrow = Wk + (o - 20) * 512; bias = bk[o - 20]; }

        const float4* xp = (const float4*)&xs[r * 516];
        const float4* wp = (const float4*)wrow;
        float a0 = 0.f, a1 = 0.f, a2 = 0.f, a3 = 0.f;
        #pragma unroll 8
        for (int q = 0; q < 128; q++) {
            float4 x = xp[q];
            float4 w = __ldg(&wp[q]);
            a0 += x.x * w.x; a1 += x.y * w.y; a2 += x.z * w.z; a3 += x.w * w.w;
        }
        float v = expf((a0 + a1) + (a2 + a3) + bias);
        int row = r0 + r;
        if (o < 10)      g_a   [row * 10 + o]        = v;
        else if (o < 20) g_b2  [row * 10 + (o - 10)] = v * LOG2E;
        else             g_kinc[row * 10 + (o - 20)] = v;
    }

    // last-block protocol
    __threadfence();
    __syncthreads();
    if (tid == 0) s_last = (atomicAdd(&g_done, 1u) == 2047u) ? 1u : 0u;
    __syncthreads();
    if (s_last) {
        if (tid == 0) __threadfence();   // acquire other blocks' stores
        __syncthreads();
        // zero GRU + wgi counters for this replay
        for (int j = tid; j < 512; j += 256) g_cnt[j] = 0;
        if (tid == 0) g_wcnt = 0;
        // cumulative k_t + att_k output
        for (int j = tid; j < 640; j += 256) {
            float acc = att_init[j];
            #pragma unroll 8
            for (int t = 0; t < TS_; t++) {
                acc += g_kinc[t * 640 + j];
                g_kinc[t * 640 + j] = acc;
                out[OFF_ATTK + t * 640 + j] = acc;
            }
        }
        __syncthreads();
        if (tid == 0) { __threadfence(); g_done = 0; }
    }
}

// ---------------- K2: phi ----------------
__global__ __launch_bounds__(512) void k_phi() {
    __shared__ float sa[10], sb[10], sk[10];
    int row = blockIdx.x;
    int tid = threadIdx.x;
    if (tid < 10)       sa[tid]      = g_a   [row * 10 + tid];
    else if (tid < 20)  sb[tid - 10] = g_b2  [row * 10 + tid - 10];
    else if (tid < 30)  sk[tid - 20] = g_kinc[row * 10 + tid - 20];
    __syncthreads();
    float s = (float)tid;
    float acc = 0.f;
    #pragma unroll
    for (int k = 0; k < 10; k++) {
        float d = sk[k] - s;
        float e = sb[k] * d * d;
        if (e < 30.f) acc += sa[k] * ex2f(-e);
    }
    g_phi[row * 512 + tid] = acc;
}

// ---------------- K3: fused w-GEMM + gi-GEMM (R3-proven tile internals) ----------------
#define AST 264
#define BST 132

__global__ __launch_bounds__(256, 2) void k_wgi(
    const float* __restrict__ c_inp, float* __restrict__ wbuf,
    const float* __restrict__ W_ih, const float* __restrict__ b_ih)
{
    __shared__ float As2[16 * AST];
    __shared__ float Bs [16 * BST];
    __shared__ unsigned s_go;
    int tid = threadIdx.x;
    int bid = blockIdx.x;
    int tx = tid & 15, ty = tid >> 4;

    if (bid < 512) {
        // ============ w = phi @ c_inp (per batch) ============
        int b  = bid >> 3;
        int m0 = ((bid >> 2) & 1) * 128, n0 = (bid & 3) * 128;

        int lrow = tid >> 2, lq = tid & 3;
        const float* Ap0 = g_phi + b * 512 + (m0 + lrow) * 32768 + lq * 4;
        const float* Ap1 = Ap0 + 64 * 32768;
        int lk = tid >> 5, nq = tid & 31;
        const float* Bp0 = c_inp + b * 512 + lk * 32768 + n0 + nq * 4;
        const float* Bp1 = Bp0 + 8 * 32768;

        float4 aR0 = *(const float4*)(Ap0);
        float4 aR1 = *(const float4*)(Ap1);
        float4 bR0 = *(const float4*)(Bp0);
        float4 bR1 = *(const float4*)(Bp1);

        u64 acc[8][4];
        #pragma unroll
        for (int i = 0; i < 8; i++)
            #pragma unroll
            for (int j = 0; j < 4; j++) acc[i][j] = 0ull;

        for (int kt = 0; kt < 32; kt++) {
            __syncthreads();
            {
                int m = 2 * lrow;
                *(u64*)&As2[(lq * 4 + 0) * AST + m]       = pack2(aR0.x, aR0.x);
                *(u64*)&As2[(lq * 4 + 1) * AST + m]       = pack2(aR0.y, aR0.y);
                *(u64*)&As2[(lq * 4 + 2) * AST + m]       = pack2(aR0.z, aR0.z);
                *(u64*)&As2[(lq * 4 + 3) * AST + m]       = pack2(aR0.w, aR0.w);
                *(u64*)&As2[(lq * 4 + 0) * AST + m + 128] = pack2(aR1.x, aR1.x);
                *(u64*)&As2[(lq * 4 + 1) * AST + m + 128] = pack2(aR1.y, aR1.y);
                *(u64*)&As2[(lq * 4 + 2) * AST + m + 128] = pack2(aR1.z, aR1.z);
                *(u64*)&As2[(lq * 4 + 3) * AST + m + 128] = pack2(aR1.w, aR1.w);
                *(float4*)&Bs[lk * BST + nq * 4]       = bR0;
                *(float4*)&Bs[(lk + 8) * BST + nq * 4] = bR1;
            }
            __syncthreads();
            if (kt < 31) {
                aR0 = *(const float4*)(Ap0 + (kt + 1) * 16);
                aR1 = *(const float4*)(Ap1 + (kt + 1) * 16);
                bR0 = *(const float4*)(Bp0 + (kt + 1) * 16 * 32768);
                bR1 = *(const float4*)(Bp1 + (kt + 1) * 16 * 32768);
            }
            #pragma unroll
            for (int kk = 0; kk < 16; kk++) {
                ulonglong2 a01 = *(const ulonglong2*)&As2[kk * AST + 8 * ty];
                ulonglong2 a23 = *(const ulonglong2*)&As2[kk * AST + 8 * ty + 4];
                ulonglong2 a45 = *(const ulonglong2*)&As2[kk * AST + 8 * ty + 128];
                ulonglong2 a67 = *(const ulonglong2*)&As2[kk * AST + 8 * ty + 132];
                ulonglong2 b01 = *(const ulonglong2*)&Bs[kk * BST + tx * 4];
                ulonglong2 b23 = *(const ulonglong2*)&Bs[kk * BST + tx * 4 + 64];
                u64 av[8] = {a01.x, a01.y, a23.x, a23.y, a45.x, a45.y, a67.x, a67.y};
                u64 bv[4] = {b01.x, b01.y, b23.x, b23.y};
                #pragma unroll
                for (int i = 0; i < 8; i++)
                    #pragma unroll
                    for (int j = 0; j < 4; j++)
                        acc[i][j] = ffma2(av[i], bv[j], acc[i][j]);
            }
        }
        float* C = wbuf + b * 512;
        #pragma unroll
        for (int i = 0; i < 8; i++) {
            int m = m0 + ((i < 4) ? (ty * 4 + i) : (ty * 4 + 64 + i - 4));
            float c0, c1, c2, c3;
            unpack2(acc[i][0], c0, c1); unpack2(acc[i][1], c2, c3);
            *(float4*)&C[(size_t)m * 32768 + n0 + tx * 4] = make_float4(c0, c1, c2, c3);
            unpack2(acc[i][2], c0, c1); unpack2(acc[i][3], c2, c3);
            *(float4*)&C[(size_t)m * 32768 + n0 + tx * 4 + 64] = make_float4(c0, c1, c2, c3);
        }
        // publish completion
        __threadfence();
        __syncthreads();
        if (tid == 0) atomicAdd(&g_wcnt, 1u);
    } else {
        // ============ gi = w @ W_ih^T + b_ih ============
        int gid = bid - 512;
        int m0 = (gid / 12) * 128, n0 = (gid % 12) * 128;

        // wait for all w tiles
        if (tid == 0) {
            while (*((volatile unsigned*)&g_wcnt) < 512u) { __nanosleep(128); }
            __threadfence();
            s_go = 1;
        }
        __syncthreads();

        int lrow = tid >> 2, lq = tid & 3;
        const float* Ap0 = wbuf + (m0 + lrow) * 512 + lq * 4;
        const float* Ap1 = Ap0 + 64 * 512;
        const float* Bp0 = W_ih + (n0 + lrow) * 512 + lq * 4;
        const float* Bp1 = Bp0 + 64 * 512;

        float4 aR0 = *(const float4*)(Ap0);
        float4 aR1 = *(const float4*)(Ap1);
        float4 bR0 = *(const float4*)(Bp0);
        float4 bR1 = *(const float4*)(Bp1);

        u64 acc[8][4];
        #pragma unroll
        for (int i = 0; i < 8; i++)
            #pragma unroll
            for (int j = 0; j < 4; j++) acc[i][j] = 0ull;

        for (int kt = 0; kt < 32; kt++) {
            __syncthreads();
            {
                int m = 2 * lrow;
                *(u64*)&As2[(lq * 4 + 0) * AST + m]       = pack2(aR0.x, aR0.x);
                *(u64*)&As2[(lq * 4 + 1) * AST + m]       = pack2(aR0.y, aR0.y);
                *(u64*)&As2[(lq * 4 + 2) * AST + m]       = pack2(aR0.z, aR0.z);
                *(u64*)&As2[(lq * 4 + 3) * AST + m]       = pack2(aR0.w, aR0.w);
                *(u64*)&As2[(lq * 4 + 0) * AST + m + 128] = pack2(aR1.x, aR1.x);
                *(u64*)&As2[(lq * 4 + 1) * AST + m + 128] = pack2(aR1.y, aR1.y);
                *(u64*)&As2[(lq * 4 + 2) * AST + m + 128] = pack2(aR1.z, aR1.z);
                *(u64*)&As2[(lq * 4 + 3) * AST + m + 128] = pack2(aR1.w, aR1.w);
                Bs[(lq * 4 + 0) * BST + lrow]       = bR0.x;
                Bs[(lq * 4 + 1) * BST + lrow]       = bR0.y;
                Bs[(lq * 4 + 2) * BST + lrow]       = bR0.z;
                Bs[(lq * 4 + 3) * BST + lrow]       = bR0.w;
                Bs[(lq * 4 + 0) * BST + lrow + 64]  = bR1.x;
                Bs[(lq * 4 + 1) * BST + lrow + 64]  = bR1.y;
                Bs[(lq * 4 + 2) * BST + lrow + 64]  = bR1.z;
                Bs[(lq * 4 + 3) * BST + lrow + 64]  = bR1.w;
            }
            __syncthreads();
            if (kt < 31) {
                aR0 = *(const float4*)(Ap0 + (kt + 1) * 16);
                aR1 = *(const float4*)(Ap1 + (kt + 1) * 16);
                bR0 = *(const float4*)(Bp0 + (kt + 1) * 16);
                bR1 = *(const float4*)(Bp1 + (kt + 1) * 16);
            }
            #pragma unroll
            for (int kk = 0; kk < 16; kk++) {
                ulonglong2 a01 = *(const ulonglong2*)&As2[kk * AST + 8 * ty];
                ulonglong2 a23 = *(const ulonglong2*)&As2[kk * AST + 8 * ty + 4];
                ulonglong2 a45 = *(const ulonglong2*)&As2[kk * AST + 8 * ty + 128];
                ulonglong2 a67 = *(const ulonglong2*)&As2[kk * AST + 8 * ty + 132];
                ulonglong2 b01 = *(const ulonglong2*)&Bs[kk * BST + tx * 4];
                ulonglong2 b23 = *(const ulonglong2*)&Bs[kk * BST + tx * 4 + 64];
                u64 av[8] = {a01.x, a01.y, a23.x, a23.y, a45.x, a45.y, a67.x, a67.y};
                u64 bv[4] = {b01.x, b01.y, b23.x, b23.y};
                #pragma unroll
                for (int i = 0; i < 8; i++)
                    #pragma unroll
                    for (int j = 0; j < 4; j++)
                        acc[i][j] = ffma2(av[i], bv[j], acc[i][j]);
            }
        }
        float4 bias0 = *(const float4*)&b_ih[n0 + tx * 4];
        float4 bias1 = *(const float4*)&b_ih[n0 + tx * 4 + 64];
        #pragma unroll
        for (int i = 0; i < 8; i++) {
            int m = m0 + ((i < 4) ? (ty * 4 + i) : (ty * 4 + 64 + i - 4));
            float c0, c1, c2, c3;
            unpack2(acc[i][0], c0, c1); unpack2(acc[i][1], c2, c3);
            *(float4*)&g_gi[(size_t)m * 1536 + n0 + tx * 4] =
                make_float4(c0 + bias0.x, c1 + bias0.y, c2 + bias0.z, c3 + bias0.w);
            unpack2(acc[i][2], c0, c1); unpack2(acc[i][3], c2, c3);
            *(float4*)&g_gi[(size_t)m * 1536 + n0 + tx * 4 + 64] =
                make_float4(c0 + bias1.x, c1 + bias1.y, c2 + bias1.z, c3 + bias1.w);
        }
    }
}

// ---------------- K4: warp-specialized persistent GRU (R8, launch #4 => profiled) ----------------
#define HROW  516
#define HBUFF (16 * HROW)
#define GRU_SMEM ((2 * HBUFF + 48 * HROW) * 4)   // 165,120 B

__global__ __launch_bounds__(384, 1) void k_gru(
    const float* __restrict__ gru_init,
    const float* __restrict__ W_hh, const float* __restrict__ b_hh,
    float* __restrict__ out)
{
    extern __shared__ float sm[];
    float* hbuf = sm;                 // [2][16][HROW]
    float* Wsm  = sm + 2 * HBUFF;     // [48][HROW], row = gate*16 + u
    int tid = threadIdx.x;
    int ug = blockIdx.x, bg = blockIdx.y;

    for (int f = tid; f < 48 * 128; f += 384) {
        int rr = f >> 7, c = f & 127;
        int gate = rr >> 4, uu = rr & 15;
        float4 v = *(const float4*)&W_hh[((size_t)(gate * 512 + ug * 16 + uu)) * 512 + c * 4];
        *(float4*)&Wsm[rr * HROW + c * 4] = v;
    }
    __syncthreads();

    if (tid < 128) {
        // ================= compute warps (R3-proven cell map) =================
        int u  = tid >> 3;
        int bp = tid & 7;
        int gu  = ug * 16 + u;
        int gb0 = bg * 16 + bp;
        int gb1 = gb0 + 8;
        float bhr = b_hh[gu], bhz = b_hh[512 + gu], bhn = b_hh[1024 + gu];
        const float* wr = &Wsm[(0  + u) * HROW];
        const float* wz = &Wsm[(16 + u) * HROW];
        const float* wn = &Wsm[(32 + u) * HROW];

        for (int t = 0; t < TS_; t++) {
            const float* gp0 = g_gi + ((size_t)(t * 64 + gb0)) * 1536 + gu;
            const float* gp1 = g_gi + ((size_t)(t * 64 + gb1)) * 1536 + gu;
            float giR0 = __ldcs(gp0), giZ0 = __ldcs(gp0 + 512), giN0 = __ldcs(gp0 + 1024);
            float giR1 = __ldcs(gp1), giZ1 = __ldcs(gp1 + 512), giN1 = __ldcs(gp1 + 1024);

            asm volatile("bar.sync 1, 384;" ::: "memory");   // h_{t-1} staged

            const float* h0 = &hbuf[(t & 1) * HBUFF + bp * HROW];
            const float* h1 = h0 + 8 * HROW;
            u64 aR0 = 0, aZ0 = 0, aN0 = 0, aR1 = 0, aZ1 = 0, aN1 = 0;
            #pragma unroll 8
            for (int hh = 0; hh < 512; hh += 4) {
                ulonglong2 hv0 = *(const ulonglong2*)&h0[hh];
                ulonglong2 hv1 = *(const ulonglong2*)&h1[hh];
                ulonglong2 r2 = *(const ulonglong2*)&wr[hh];
                ulonglong2 z2 = *(const ulonglong2*)&wz[hh];
                ulonglong2 n2 = *(const ulonglong2*)&wn[hh];
                aR0 = ffma2(hv0.x, r2.x, aR0); aR0 = ffma2(hv0.y, r2.y, aR0);
                aZ0 = ffma2(hv0.x, z2.x, aZ0); aZ0 = ffma2(hv0.y, z2.y, aZ0);
                aN0 = ffma2(hv0.x, n2.x, aN0); aN0 = ffma2(hv0.y, n2.y, aN0);
                aR1 = ffma2(hv1.x, r2.x, aR1); aR1 = ffma2(hv1.y, r2.y, aR1);
                aZ1 = ffma2(hv1.x, z2.x, aZ1); aZ1 = ffma2(hv1.y, z2.y, aZ1);
                aN1 = ffma2(hv1.x, n2.x, aN1); aN1 = ffma2(hv1.y, n2.y, aN1);
            }
            float lo, hi;
            unpack2(aR0, lo, hi); float sR0 = lo + hi;
            unpack2(aZ0, lo, hi); float sZ0 = lo + hi;
            unpack2(aN0, lo, hi); float sN0 = lo + hi;
            unpack2(aR1, lo, hi); float sR1 = lo + hi;
            unpack2(aZ1, lo, hi); float sZ1 = lo + hi;
            unpack2(aN1, lo, hi); float sN1 = lo + hi;

            float hp0 = hbuf[(t & 1) * HBUFF + bp * HROW + gu];
            float hp1 = hbuf[(t & 1) * HBUFF + (bp + 8) * HROW + gu];
            float r0 = sigmf(giR0 + sR0 + bhr);
            float z0 = sigmf(giZ0 + sZ0 + bhz);
            float n0v = tanhf(giN0 + r0 * (sN0 + bhn));
            float hn0 = (1.f - z0) * n0v + z0 * hp0;
            float r1 = sigmf(giR1 + sR1 + bhr);
            float z1 = sigmf(giZ1 + sZ1 + bhz);
            float n1v = tanhf(giN1 + r1 * (sN1 + bhn));
            float hn1 = (1.f - z1) * n1v + z1 * hp1;

            g_h[((t + 1) & 1) * 32768 + gb0 * 512 + gu] = hn0;
            g_h[((t + 1) & 1) * 32768 + gb1 * 512 + gu] = hn1;
            asm volatile("bar.sync 2, 128;" ::: "memory");
            if (tid == 0) {
                __threadfence();
                atomicAdd(&g_cnt[bg * 32], 1u);
            }
            out[(size_t)t * 32768 + gb0 * 512 + gu] = hn0;
            out[(size_t)t * 32768 + gb1 * 512 + gu] = hn1;
        }
    } else if (tid < 256) {
        // ================= staging warps =================
        int stid = tid - 128;
        volatile unsigned* bar = &g_cnt[bg * 32];
        for (int t = 0; t < TS_; t++) {
            const float4* src;
            if (t == 0) {
                src = (const float4*)(gru_init + bg * 8192);
            } else {
                if (stid == 0) {
                    unsigned target = 32u * (unsigned)t;
                    while (*bar < target) { }
                    __threadfence();
                }
                asm volatile("bar.sync 3, 128;" ::: "memory");
                src = (const float4*)(g_h + (t & 1) * 32768 + bg * 8192);
            }
            float* dst = &hbuf[(t & 1) * HBUFF];
            #pragma unroll
            for (int c = 0; c < 16; c++) {
                int i = c * 128 + stid;
                float4 v = __ldcg(&src[i]);
                *(float4*)&dst[(i >> 7) * HROW + (i & 127) * 4] = v;
            }
            asm volatile("bar.sync 1, 384;" ::: "memory");
        }
    } else {
        // idle warps kept for symmetric bar1 count
        for (int t = 0; t < TS_; t++) {
            asm volatile("bar.sync 1, 384;" ::: "memory");
        }
    }
}

// ---------------- host ----------------
extern "C" void kernel_launch(void* const* d_in, const int* in_sizes, int n_in,
                              void* d_out, int out_size)
{
    const float* c_inp    = (const float*)d_in[0];
    const float* inp      = (const float*)d_in[1];
    const float* gru_init = (const float*)d_in[2];
    const float* att_init = (const float*)d_in[3];
    const float* Wa = (const float*)d_in[4];  const float* ba = (const float*)d_in[5];
    const float* Wb = (const float*)d_in[6];  const float* bb = (const float*)d_in[7];
    const float* Wk = (const float*)d_in[8];  const float* bk = (const float*)d_in[9];
    const float* W_ih = (const float*)d_in[10]; const float* b_ih = (const float*)d_in[11];
    const float* W_hh = (const float*)d_in[12]; const float* b_hh = (const float*)d_in[13];
    float* out = (float*)d_out;

    cudaFuncSetAttribute(k_gru, cudaFuncAttributeMaxDynamicSharedMemorySize, GRU_SMEM);

    // 4 launches: k_gru is launch #4 (the position ncu captures)
    k_abk_cum<<<2048, 256>>>(inp, Wa, ba, Wb, bb, Wk, bk, att_init, out);
    k_phi    <<<16384, 512>>>();
    k_wgi    <<<2048, 256>>>(c_inp, out + OFF_ATTW, W_ih, b_ih);
    k_gru    <<<dim3(32, 4), 384, GRU_SMEM>>>(gru_init, W_hh, b_hh, out);
}